// round 8
// baseline (speedup 1.0000x reference)
#include <cuda_runtime.h>

#define NN    8192
#define NT    1024
#define EPB   8           // NT*EPB == NN
#define MAXO  300
#define NW    (NN/64)     // 128 u64 words per mask row
#define DPQ   16          // greedy candidate-ring depth (power of 2)

typedef unsigned long long u64;

// Static device scratch (no allocation). Fully rewritten every launch.
__device__ float4 g_boxes[NN];
__device__ float  g_area[NN];
__device__ int    g_sidx[NN];
__device__ __align__(16) u64 g_mask[(size_t)NN * NW];   // 8MB, self+above-diag bits

__device__ __forceinline__ void cmpex(u64& a, u64& b, bool up) {
  u64 x = a, y = b;
  if ((x > y) == up) { a = y; b = x; }
}

__device__ __forceinline__ unsigned s2u(const void* p) {
  unsigned r;
  asm("{ .reg .u64 t; cvta.to.shared.u64 t, %1; cvt.u32.u64 %0, t; }"
      : "=r"(r) : "l"(p));
  return r;
}

// ---------------------------------------------------------------------------
// Kernel A: bitonic sort of (~score_bits<<32 | idx). 1024 threads, 8 elems
// each (blocked). jj<=4: register passes. jj=8..128: shfl_xor passes.
// jj>=256: smem passes. 32 warps hide shfl/LDS/barrier latency.
// ---------------------------------------------------------------------------
__global__ __launch_bounds__(NT, 1)
void sort_kernel(const float4* __restrict__ rois,
                 const float*  __restrict__ scores,
                 float* __restrict__ out) {
  extern __shared__ u64 sk[];   // 64KB
  const int tid  = threadIdx.x;
  const int base = tid * EPB;

  for (int p = tid; p < NN; p += NT) {
    unsigned sb = __float_as_uint(scores[p]);  // scores >= 0 -> bits monotone
    sk[p] = (((u64)(~sb)) << 32) | (unsigned)p;
  }
  if (tid < MAXO) out[tid] = -1.0f;
  __syncthreads();

  u64 v[EPB];
#pragma unroll
  for (int e = 0; e < EPB; e++) v[e] = sk[base + e];

  // k=2 (jj=1), k=4 (jj=2,1): direction depends on e only
#pragma unroll
  for (int e = 0; e < EPB; e++) { int e2 = e ^ 1; if (e2 > e) cmpex(v[e], v[e2], (e & 2) == 0); }
#pragma unroll
  for (int jj = 2; jj; jj >>= 1)
#pragma unroll
    for (int e = 0; e < EPB; e++) { int e2 = e ^ jj; if (e2 > e) cmpex(v[e], v[e2], (e & 4) == 0); }
  // k=8: direction uniform per thread
  {
    bool up = ((base & 8) == 0);
#pragma unroll
    for (int jj = 4; jj; jj >>= 1)
#pragma unroll
      for (int e = 0; e < EPB; e++) { int e2 = e ^ jj; if (e2 > e) cmpex(v[e], v[e2], up); }
  }

  for (int k = 16; k <= NN; k <<= 1) {
    const bool up = ((base & k) == 0);
    int jj = k >> 1;
    if (jj >= 256) {                      // cross-warp strides: smem passes
#pragma unroll
      for (int e = 0; e < EPB; e++) sk[base + e] = v[e];
      __syncthreads();
      for (; jj >= 256; jj >>= 1) {
        for (int pp = tid; pp < NN / 2; pp += NT) {
          int p = ((pp & ~(jj - 1)) << 1) | (pp & (jj - 1));
          int q = p | jj;
          bool u2 = ((p & k) == 0);
          u64 a = sk[p], b = sk[q];
          if ((a > b) == u2) { sk[p] = b; sk[q] = a; }
        }
        __syncthreads();
      }
#pragma unroll
      for (int e = 0; e < EPB; e++) v[e] = sk[base + e];
      jj = 128;
    }
    for (; jj >= 8; jj >>= 1) {           // in-warp: shfl passes
      int s = jj >> 3;
      bool takemin = (((tid & s) == 0) == up);
#pragma unroll
      for (int e = 0; e < EPB; e++) {
        u64 o  = __shfl_xor_sync(0xFFFFFFFFu, v[e], s);
        u64 mn = (v[e] < o) ? v[e] : o;
        u64 mx = (v[e] < o) ? o : v[e];
        v[e] = takemin ? mn : mx;
      }
    }
#pragma unroll
    for (int j2 = 4; j2; j2 >>= 1)        // in-thread register passes
#pragma unroll
      for (int e = 0; e < EPB; e++) { int e2 = e ^ j2; if (e2 > e) cmpex(v[e], v[e2], up); }
  }

#pragma unroll
  for (int e = 0; e < EPB; e++) {
    int p  = base + e;
    int id = (int)(unsigned)(v[e] & 0xFFFFFFFFull);
    g_sidx[p] = id;
    float4 bb = rois[id];
    g_boxes[p] = bb;
    g_area[p] = __fmul_rn(__fsub_rn(bb.z, bb.x), __fsub_rn(bb.w, bb.y));
  }
}

// ---------------------------------------------------------------------------
// Kernel B: suppression bitmask (unchanged from R6/R7). Block (cb, rg):
// 256 threads, thread t handles row i = rg*256+t, computes mask word cb.
// Bit e set <=> j = cb*64+e >= i AND IoU(i,j) > 0.5 (diagonal bit set).
// ---------------------------------------------------------------------------
__global__ __launch_bounds__(256, 8)
void mask_kernel() {
  const int cb = blockIdx.x;
  const int t  = threadIdx.x;
  const int i  = blockIdx.y * 256 + t;
  const int jbase = cb * 64;

  __shared__ float4 cbox[64];
  __shared__ float  carea[64];
  if (t < 64) { cbox[t] = g_boxes[jbase + t]; carea[t] = g_area[jbase + t]; }
  __syncthreads();

  if (jbase + 63 < i) { g_mask[(size_t)i * NW + cb] = 0ull; return; }

  const float4 bi = g_boxes[i];
  const float  ai = g_area[i];
  u64 bits = 0;
#pragma unroll 4
  for (int e = 0; e < 64; e++) {
    float4 bj = cbox[e];
    float lx = fmaxf(bi.x, bj.x);
    float ly = fmaxf(bi.y, bj.y);
    float rx = fminf(bi.z, bj.z);
    float ry = fminf(bi.w, bj.w);
    float ww = fmaxf(__fsub_rn(rx, lx), 0.0f);
    float hh = fmaxf(__fsub_rn(ry, ly), 0.0f);
    float inter = __fmul_rn(ww, hh);
    float uni   = __fsub_rn(__fadd_rn(ai, carea[e]), inter);
    // decide (inter/uni > 0.5) exactly: margin test, IEEE-divide fallback
    float d   = __fmaf_rn(-0.5f, uni, inter);
    float tol = 1e-6f * uni;
    bool sup;
    if (d > tol)       sup = true;
    else if (d < -tol) sup = false;
    else               sup = (__fdiv_rn(inter, uni) > 0.5f);
    bits |= ((u64)sup) << e;
  }
  if (i > jbase) bits &= (~0ull) << (i - jbase);   // keep only j >= i
  g_mask[(size_t)i * NW + cb] = bits;
}

// ---------------------------------------------------------------------------
// Kernel C: single-warp greedy, candidate-only cp.async prefetch.
// Lane l owns columns [256l, 256l+256) as R0..R3. The issue cursor walks
// free-at-issue-time positions (broadcast rem word, stale bits harmless);
// their rows are prefetched DPQ slots ahead into an smem ring. Consume side
// rechecks the bit (skips mispredicts) and ORs the prefetched row on keeps.
// Exactly one commit_group per slot keeps wait_group DPQ-1 exact.
// All branches are warp-uniform (candidates/outc identical in every lane).
// ---------------------------------------------------------------------------
__global__ void greedy_kernel(float* __restrict__ out) {
  __shared__ __align__(16) u64 ring[DPQ][NW];   // 16KB
  const int lane = threadIdx.x;
  u64 R0 = 0, R1 = 0, R2 = 0, R3 = 0;
  int cq[DPQ];                 // candidate queue (uniform, static-indexed)
  int iw = 0;  u64 iww = 0;    // issue cursor: word idx + claimed/suppressed bits
  int outc = 0;

#define FETCHW(WW, DST) do {                                                  \
    int _w = (WW);                                                            \
    u64 _x = ((_w & 3) == 0) ? R0 : ((_w & 3) == 1) ? R1                      \
           : ((_w & 3) == 2) ? R2 : R3;                                       \
    DST = __shfl_sync(0xFFFFFFFFu, _x, _w >> 2);                              \
  } while (0)

#define ISSUE_NEXT(CR) do {                                                   \
    CR = NN;                                                                  \
    for (;;) {                                                                \
      u64 _f = ~iww;                                                          \
      if (_f) { int _b = __ffsll((long long)_f) - 1;                          \
                iww |= (1ull << _b); CR = iw * 64 + _b; break; }              \
      if (++iw >= NW) { iww = ~0ull; break; }                                 \
      FETCHW(iw, iww);                                                        \
    }                                                                         \
  } while (0)

#define ISSUE_ROW(SLOT, C) do {                                               \
    unsigned long long _ga;                                                   \
    asm("cvta.to.global.u64 %0, %1;" : "=l"(_ga)                              \
        : "l"((const void*)((const char*)(g_mask + (size_t)(C) * NW)          \
                            + lane * 32)));                                   \
    unsigned _sa = s2u(&ring[SLOT][0]) + (unsigned)(lane * 32);               \
    asm volatile(                                                             \
        "cp.async.cg.shared.global [%0], [%1], 16;\n\t"                       \
        "cp.async.cg.shared.global [%2], [%3], 16;\n\t"                       \
        :: "r"(_sa), "l"(_ga), "r"(_sa + 16), "l"(_ga + 16) : "memory");      \
  } while (0)

  // prime the ring: first DPQ candidates (rem empty -> positions 0..15)
#pragma unroll
  for (int s = 0; s < DPQ; s++) {
    int c; ISSUE_NEXT(c);
    cq[s] = c;
    if (c < NN) ISSUE_ROW(s, c);
    asm volatile("cp.async.commit_group;" ::: "memory");
  }

  for (;;) {
#pragma unroll
    for (int s = 0; s < DPQ; s++) {
      asm volatile("cp.async.wait_group %0;" :: "n"(DPQ - 1) : "memory");
      int c = cq[s];
      if (c >= NN) goto done;
      u64 w; FETCHW(c >> 6, w);
      if (!((w >> (c & 63)) & 1ull)) {            // still free -> KEPT
        if (lane == 0) out[outc] = (float)g_sidx[c];
        if (++outc >= MAXO) goto done;
        const ulonglong2* r =
            reinterpret_cast<const ulonglong2*>(&ring[s][0]);
        ulonglong2 a = r[2 * lane];
        ulonglong2 b = r[2 * lane + 1];
        R0 |= a.x; R1 |= a.y; R2 |= b.x; R3 |= b.y;
      }
      int cn; ISSUE_NEXT(cn);
      cq[s] = cn;
      if (cn < NN) ISSUE_ROW(s, cn);
      asm volatile("cp.async.commit_group;" ::: "memory");
    }
  }
done: ;
}

// ---------------------------------------------------------------------------
extern "C" void kernel_launch(void* const* d_in, const int* in_sizes, int n_in,
                              void* d_out, int out_size) {
  const void* a0 = d_in[0];
  const void* a1 = d_in[1];
  const float4* rois;
  const float*  scores;
  if (in_sizes[0] >= in_sizes[1]) { rois = (const float4*)a0; scores = (const float*)a1; }
  else                            { rois = (const float4*)a1; scores = (const float*)a0; }

  cudaFuncSetAttribute(sort_kernel, cudaFuncAttributeMaxDynamicSharedMemorySize,
                       NN * (int)sizeof(u64));
  sort_kernel<<<1, NT, NN * sizeof(u64)>>>(rois, scores, (float*)d_out);
  mask_kernel<<<dim3(NW, NN / 256), 256>>>();
  greedy_kernel<<<1, 32>>>((float*)d_out);
}

// round 9
// speedup vs baseline: 1.1513x; 1.1513x over previous
#include <cuda_runtime.h>

#define NN    8192
#define MAXO  300
#define NW    (NN/64)     // 128 u64 words per mask row
#define BW    32          // greedy batch width
#define CH    2048        // chunk size for chunk_sort
#define CT    256         // chunk_sort threads (EPB 8)
#define MT    1024        // merge threads (EPB 8)

typedef unsigned long long u64;

// Static device scratch (no allocation). Fully rewritten every launch.
__device__ u64    g_keys[NN];
__device__ float4 g_boxes[NN];
__device__ float  g_area[NN];
__device__ int    g_sidx[NN];
__device__ __align__(16) u64 g_mask[(size_t)NN * NW];   // 8MB, self+above-diag bits

__device__ __forceinline__ void cmpex(u64& a, u64& b, bool up) {
  u64 x = a, y = b;
  if ((x > y) == up) { a = y; b = x; }
}

// ---------------------------------------------------------------------------
// Kernel A1: chunk bitonic sort. 4 blocks x 256 threads, each sorts a 2048-
// element chunk of (~score_bits<<32 | idx) keys, running the GLOBAL bitonic
// network's phases k=2..2048 (directions from global index -> valid prefix).
// ---------------------------------------------------------------------------
__global__ __launch_bounds__(CT, 1)
void chunk_sort(const float* __restrict__ scores) {
  __shared__ u64 sk[CH];
  const int tid   = threadIdx.x;
  const int cbase = blockIdx.x * CH;
  for (int p = tid; p < CH; p += CT) {
    unsigned sb = __float_as_uint(scores[cbase + p]);  // scores>=0: bits monotone
    sk[p] = (((u64)(~sb)) << 32) | (unsigned)(cbase + p);
  }
  __syncthreads();
  const int lbase = tid * 8;
  const int gbase = cbase + lbase;
  u64 v[8];
#pragma unroll
  for (int e = 0; e < 8; e++) v[e] = sk[lbase + e];

#pragma unroll
  for (int e = 0; e < 8; e++) { int e2 = e ^ 1; if (e2 > e) cmpex(v[e], v[e2], (e & 2) == 0); }
#pragma unroll
  for (int jj = 2; jj; jj >>= 1)
#pragma unroll
    for (int e = 0; e < 8; e++) { int e2 = e ^ jj; if (e2 > e) cmpex(v[e], v[e2], (e & 4) == 0); }
  {
    bool up = ((gbase & 8) == 0);
#pragma unroll
    for (int jj = 4; jj; jj >>= 1)
#pragma unroll
      for (int e = 0; e < 8; e++) { int e2 = e ^ jj; if (e2 > e) cmpex(v[e], v[e2], up); }
  }

  for (int k = 16; k <= CH; k <<= 1) {
    const bool up = ((gbase & k) == 0);
    int jj = k >> 1;
    if (jj >= 256) {
#pragma unroll
      for (int e = 0; e < 8; e++) sk[lbase + e] = v[e];
      __syncthreads();
      for (; jj >= 256; jj >>= 1) {
        for (int pp = tid; pp < CH / 2; pp += CT) {
          int p = ((pp & ~(jj - 1)) << 1) | (pp & (jj - 1));
          int q = p | jj;
          bool u2 = (((cbase + p) & k) == 0);
          u64 a = sk[p], b = sk[q];
          if ((a > b) == u2) { sk[p] = b; sk[q] = a; }
        }
        __syncthreads();
      }
#pragma unroll
      for (int e = 0; e < 8; e++) v[e] = sk[lbase + e];
    }
    for (; jj >= 8; jj >>= 1) {
      int s = jj >> 3;
      bool takemin = (((tid & s) == 0) == up);
#pragma unroll
      for (int e = 0; e < 8; e++) {
        u64 o  = __shfl_xor_sync(0xFFFFFFFFu, v[e], s);
        u64 mn = (v[e] < o) ? v[e] : o;
        u64 mx = (v[e] < o) ? o : v[e];
        v[e] = takemin ? mn : mx;
      }
    }
#pragma unroll
    for (int j2 = 4; j2; j2 >>= 1)
#pragma unroll
      for (int e = 0; e < 8; e++) { int e2 = e ^ j2; if (e2 > e) cmpex(v[e], v[e2], up); }
  }
#pragma unroll
  for (int e = 0; e < 8; e++) g_keys[gbase + e] = v[e];
}

// ---------------------------------------------------------------------------
// Kernel A2: bitonic merge phases k=4096, 8192 (25 passes) on one block of
// 1024 threads; emits sorted boxes/areas/sidx and inits the output.
// ---------------------------------------------------------------------------
__global__ __launch_bounds__(MT, 1)
void merge_kernel(const float4* __restrict__ rois, float* __restrict__ out) {
  extern __shared__ u64 sk[];   // 64KB
  const int tid  = threadIdx.x;
  const int base = tid * 8;
  if (tid < MAXO) out[tid] = -1.0f;
  u64 v[8];
#pragma unroll
  for (int e = 0; e < 8; e++) v[e] = g_keys[base + e];

  for (int k = 2 * CH; k <= NN; k <<= 1) {
    const bool up = ((base & k) == 0);
    int jj = k >> 1;
#pragma unroll
    for (int e = 0; e < 8; e++) sk[base + e] = v[e];
    __syncthreads();
    for (; jj >= 256; jj >>= 1) {
      for (int pp = tid; pp < NN / 2; pp += MT) {
        int p = ((pp & ~(jj - 1)) << 1) | (pp & (jj - 1));
        int q = p | jj;
        bool u2 = ((p & k) == 0);
        u64 a = sk[p], b = sk[q];
        if ((a > b) == u2) { sk[p] = b; sk[q] = a; }
      }
      __syncthreads();
    }
#pragma unroll
    for (int e = 0; e < 8; e++) v[e] = sk[base + e];
    for (; jj >= 8; jj >>= 1) {
      int s = jj >> 3;
      bool takemin = (((tid & s) == 0) == up);
#pragma unroll
      for (int e = 0; e < 8; e++) {
        u64 o  = __shfl_xor_sync(0xFFFFFFFFu, v[e], s);
        u64 mn = (v[e] < o) ? v[e] : o;
        u64 mx = (v[e] < o) ? o : v[e];
        v[e] = takemin ? mn : mx;
      }
    }
#pragma unroll
    for (int j2 = 4; j2; j2 >>= 1)
#pragma unroll
      for (int e = 0; e < 8; e++) { int e2 = e ^ j2; if (e2 > e) cmpex(v[e], v[e2], up); }
  }

#pragma unroll
  for (int e = 0; e < 8; e++) {
    int p  = base + e;
    int id = (int)(unsigned)(v[e] & 0xFFFFFFFFull);
    g_sidx[p] = id;
    float4 bb = rois[id];
    g_boxes[p] = bb;
    g_area[p] = __fmul_rn(__fsub_rn(bb.z, bb.x), __fsub_rn(bb.w, bb.y));
  }
}

// ---------------------------------------------------------------------------
// Kernel B: suppression bitmask (unchanged). Bit e of word cb of row i set
// <=> j = cb*64+e >= i AND IoU(i,j) > 0.5 (diagonal bit set).
// ---------------------------------------------------------------------------
__global__ __launch_bounds__(256, 8)
void mask_kernel() {
  const int cb = blockIdx.x;
  const int t  = threadIdx.x;
  const int i  = blockIdx.y * 256 + t;
  const int jbase = cb * 64;

  __shared__ float4 cbox[64];
  __shared__ float  carea[64];
  if (t < 64) { cbox[t] = g_boxes[jbase + t]; carea[t] = g_area[jbase + t]; }
  __syncthreads();

  if (jbase + 63 < i) { g_mask[(size_t)i * NW + cb] = 0ull; return; }

  const float4 bi = g_boxes[i];
  const float  ai = g_area[i];
  u64 bits = 0;
#pragma unroll 4
  for (int e = 0; e < 64; e++) {
    float4 bj = cbox[e];
    float lx = fmaxf(bi.x, bj.x);
    float ly = fmaxf(bi.y, bj.y);
    float rx = fminf(bi.z, bj.z);
    float ry = fminf(bi.w, bj.w);
    float ww = fmaxf(__fsub_rn(rx, lx), 0.0f);
    float hh = fmaxf(__fsub_rn(ry, ly), 0.0f);
    float inter = __fmul_rn(ww, hh);
    float uni   = __fsub_rn(__fadd_rn(ai, carea[e]), inter);
    // decide (inter/uni > 0.5) exactly: margin test, IEEE-divide fallback
    float d   = __fmaf_rn(-0.5f, uni, inter);
    float tol = 1e-6f * uni;
    bool sup;
    if (d > tol)       sup = true;
    else if (d < -tol) sup = false;
    else               sup = (__fdiv_rn(inter, uni) > 0.5f);
    bits |= ((u64)sup) << e;
  }
  if (i > jbase) bits &= (~0ull) << (i - jbase);   // keep only j >= i
  g_mask[(size_t)i * NW + cb] = bits;
}

// ---------------------------------------------------------------------------
// Kernel C: single-warp BATCHED greedy. Lane l owns rem words 4l..4l+3
// (positions [256l, 256l+256)). Per batch of 32 candidates: rows prefetched
// 2 batches ahead via cp.async; resolution uses the intra-batch suppression
// matrix S (lane l, bit m = row c_m suppresses c_l) + a ballot loop; kept
// rows are OR'd into rem. Exactly equivalent to serial greedy.
// ---------------------------------------------------------------------------
__device__ __forceinline__ void extract_issue(
    int buf, u64 R0, u64 R1, u64 R2, u64 R3, int& cursor,
    int* cand, u64* ring, int lane)
{
  const unsigned FULL = 0xFFFFFFFFu;
  cand[buf * BW + lane] = NN;
  __syncwarp();
  u64 F0 = ~R0, F1 = ~R1, F2 = ~R2, F3 = ~R3;
  int cnt = 0;
#pragma unroll
  for (int q = 0; q < 4; q++) {
    u64& F = (q == 0) ? F0 : (q == 1) ? F1 : (q == 2) ? F2 : F3;
    int lo = cursor - (lane * 4 + q) * 64;
    if (lo >= 64) F = 0ull;
    else if (lo > 0) F &= (~0ull) << lo;
    cnt += __popcll(F);
  }
  int x = cnt;
#pragma unroll
  for (int off = 1; off < 32; off <<= 1) {
    int y = __shfl_up_sync(FULL, x, off);
    if (lane >= off) x += y;
  }
  int total = __shfl_sync(FULL, x, 31);
  int rank  = x - cnt;
#pragma unroll
  for (int q = 0; q < 4; q++) {
    u64 F = (q == 0) ? F0 : (q == 1) ? F1 : (q == 2) ? F2 : F3;
    while (F && rank < BW) {
      int b = __ffsll((long long)F) - 1;
      cand[buf * BW + rank] = (lane * 4 + q) * 64 + b;
      rank++;
      F &= F - 1;
    }
  }
  __syncwarp();
  int numsel = total < BW ? total : BW;
  cursor = numsel ? (cand[buf * BW + numsel - 1] + 1) : NN;
  u64* rb = ring + (size_t)buf * BW * NW;
  for (int m = 0; m < BW; m++) {
    int c = cand[buf * BW + m];
    if (c < NN) {
      unsigned long long ga;
      asm("cvta.to.global.u64 %0, %1;" : "=l"(ga)
          : "l"((const void*)((const char*)(g_mask + (size_t)c * NW) + lane * 32)));
      unsigned sa;
      asm("{ .reg .u64 t; cvta.to.shared.u64 t, %1; cvt.u32.u64 %0, t; }" : "=r"(sa)
          : "l"((const void*)((const char*)(rb + (size_t)m * NW) + lane * 32)));
      asm volatile("cp.async.cg.shared.global [%0], [%1], 16;\n\t"
                   "cp.async.cg.shared.global [%2], [%3], 16;\n\t"
                   :: "r"(sa), "l"(ga), "r"(sa + 16), "l"(ga + 16) : "memory");
    }
  }
  asm volatile("cp.async.commit_group;" ::: "memory");
}

__device__ __forceinline__ bool resolve_batch(
    int buf, u64& R0, u64& R1, u64& R2, u64& R3,
    int& outc, int* cand, u64* ring, int lane, float* out)
{
  const unsigned FULL = 0xFFFFFFFFu;
  asm volatile("cp.async.wait_group 1;" ::: "memory");
  __syncwarp();
  int  c     = cand[buf * BW + lane];
  bool valid = c < NN;
  if (!__ballot_sync(FULL, valid)) return false;
  int cc = valid ? c : 0;
  int w = cc >> 6, owner = w >> 2, sub = w & 3;
  u64 x0 = __shfl_sync(FULL, R0, owner);
  u64 x1 = __shfl_sync(FULL, R1, owner);
  u64 x2 = __shfl_sync(FULL, R2, owner);
  u64 x3 = __shfl_sync(FULL, R3, owner);
  u64 xv = (sub & 2) ? ((sub & 1) ? x3 : x2) : ((sub & 1) ? x1 : x0);
  bool pre = valid && !((xv >> (cc & 63)) & 1ull);

  const u64* rb = ring + (size_t)buf * BW * NW;
  unsigned S = 0;
#pragma unroll
  for (int m = 0; m < BW; m++)
    S |= (unsigned)((rb[(size_t)m * NW + w] >> (cc & 63)) & 1ull) << m;

  unsigned rest = __ballot_sync(FULL, pre);
  unsigned kept = 0;
  while (rest) {                             // uniform loop; steps = keeps
    int m = __ffs(rest) - 1;
    kept |= 1u << m;
    unsigned supm = __ballot_sync(FULL, (S >> m) & 1u);
    rest &= ~(supm | (1u << m));
  }
  unsigned mm = kept;
  while (mm) {                               // OR kept rows into rem
    int m = __ffs(mm) - 1;
    mm &= mm - 1;
    const ulonglong2* rp =
        reinterpret_cast<const ulonglong2*>(rb + (size_t)m * NW) + 2 * lane;
    ulonglong2 a = rp[0], b = rp[1];
    R0 |= a.x; R1 |= a.y; R2 |= b.x; R3 |= b.y;
  }
  int cntk = __popc(kept);
  if ((kept >> lane) & 1u) {
    int rank = __popc(kept & ((1u << lane) - 1u));
    if (outc + rank < MAXO) out[outc + rank] = (float)g_sidx[c];
  }
  outc += cntk;
  return outc < MAXO;
}

__global__ void greedy_kernel(float* __restrict__ out) {
  extern __shared__ u64 dsm[];               // ring[2][BW][NW] + cand[2][BW]
  u64* ring = dsm;
  int* cand = (int*)(dsm + 2 * BW * NW);
  const int lane = threadIdx.x;
  u64 R0 = 0, R1 = 0, R2 = 0, R3 = 0;
  int cursor = 0, outc = 0;

  extract_issue(0, R0, R1, R2, R3, cursor, cand, ring, lane);
  extract_issue(1, R0, R1, R2, R3, cursor, cand, ring, lane);
  int buf = 0;
  for (;;) {
    if (!resolve_batch(buf, R0, R1, R2, R3, outc, cand, ring, lane, out)) break;
    extract_issue(buf, R0, R1, R2, R3, cursor, cand, ring, lane);
    buf ^= 1;
  }
}

// ---------------------------------------------------------------------------
extern "C" void kernel_launch(void* const* d_in, const int* in_sizes, int n_in,
                              void* d_out, int out_size) {
  const void* a0 = d_in[0];
  const void* a1 = d_in[1];
  const float4* rois;
  const float*  scores;
  if (in_sizes[0] >= in_sizes[1]) { rois = (const float4*)a0; scores = (const float*)a1; }
  else                            { rois = (const float4*)a1; scores = (const float*)a0; }

  const int merge_smem  = NN * (int)sizeof(u64);                 // 64KB
  const int greedy_smem = 2 * BW * NW * (int)sizeof(u64) + 2 * BW * (int)sizeof(int);
  cudaFuncSetAttribute(merge_kernel, cudaFuncAttributeMaxDynamicSharedMemorySize,
                       merge_smem);
  cudaFuncSetAttribute(greedy_kernel, cudaFuncAttributeMaxDynamicSharedMemorySize,
                       greedy_smem);

  chunk_sort<<<NN / CH, CT>>>(scores);
  merge_kernel<<<1, MT, merge_smem>>>(rois, (float*)d_out);
  mask_kernel<<<dim3(NW, NN / 256), 256>>>();
  greedy_kernel<<<1, 32, greedy_smem>>>((float*)d_out);
}